// round 7
// baseline (speedup 1.0000x reference)
#include <cuda_runtime.h>
#include <math.h>
#include <float.h>

// Problem constants (fixed by setup_inputs)
#define BMAX 2
#define NMAX 8192
#define GMAX 96
#define KMAX 128
#define RAD  0.1f
#define RAD2 0.01f      // float32 nearest to python 0.1*0.1 (matches JAX)
#define CMAXF 8192      // max flattened cells supported (data -> gdprod = 1000)
#define NBLK 148        // <= SM count (B300 148 / GB300 152): all co-resident
#define TPB  1024

struct GridInfo {
    float lx, ly, lz;
    int g0, g1, g2;
    int s0, s1;
    int gdprod;
};

__device__ GridInfo     g_grid[BMAX];
__device__ int          g_idx[BMAX][NMAX];
__device__ float4       g_nlocs[BMAX][NMAX];
__device__ int          g_start[BMAX][CMAXF + 1];
__device__ volatile int g_done[BMAX];   // zero-init; reset by last block each run
__device__ int          g_fin;          // finish counter, reset each run

// ---------------------------------------------------------------------------
// Sort body (R5-proven): one block, 1024 threads, all phases in smem.
// smem layout: loc[3N] | cid[N] | idx[N] | start[CMAXF+1]
// ---------------------------------------------------------------------------
__device__ void sort_body(int b, const float* __restrict__ locs,
                          float* __restrict__ out_idxs,
                          float* __restrict__ out_nlocs,
                          int N, float* shf)
{
    float* s_loc  = shf;                          // [NMAX*3]
    int*  s_cid   = (int*)(s_loc + NMAX * 3);     // [NMAX]
    int*  s_idx   = s_cid + NMAX;                 // [NMAX]
    int*  s_start = s_idx + NMAX;                 // [CMAXF+1]
    int*  s_part  = s_idx;                        // alias: scan partials

    __shared__ float s_wmn[32][3], s_wmx[32][3];
    __shared__ float s_lo[3], s_hi[3];

    const int t = threadIdx.x;
    const int lane = t & 31;
    const int wid  = t >> 5;

    // ---- 0) stage locs into smem, coalesced float4 ----
    {
        const float* Lg = locs + (size_t)b * N * 3;
        int n4 = (N * 3) >> 2;
        const float4* L4 = (const float4*)Lg;
        float4* S4 = (float4*)s_loc;
        for (int k = t; k < n4; k += TPB) S4[k] = L4[k];
        for (int k = (n4 << 2) + t; k < N * 3; k += TPB) s_loc[k] = Lg[k];
    }
    __syncthreads();

    // ---- 1) min/max, warp shuffles ----
    float mn[3] = { FLT_MAX, FLT_MAX, FLT_MAX };
    float mx[3] = { -FLT_MAX, -FLT_MAX, -FLT_MAX };
    for (int i = t; i < N; i += TPB) {
        #pragma unroll
        for (int d = 0; d < 3; d++) {
            float v = s_loc[i * 3 + d];
            mn[d] = fminf(mn[d], v);
            mx[d] = fmaxf(mx[d], v);
        }
    }
    #pragma unroll
    for (int d = 0; d < 3; d++) {
        #pragma unroll
        for (int o = 16; o > 0; o >>= 1) {
            mn[d] = fminf(mn[d], __shfl_down_sync(0xffffffffu, mn[d], o));
            mx[d] = fmaxf(mx[d], __shfl_down_sync(0xffffffffu, mx[d], o));
        }
        if (lane == 0) { s_wmn[wid][d] = mn[d]; s_wmx[wid][d] = mx[d]; }
    }
    __syncthreads();
    if (wid == 0) {
        float a[3], z[3];
        #pragma unroll
        for (int d = 0; d < 3; d++) { a[d] = s_wmn[lane][d]; z[d] = s_wmx[lane][d]; }
        #pragma unroll
        for (int d = 0; d < 3; d++) {
            #pragma unroll
            for (int o = 16; o > 0; o >>= 1) {
                a[d] = fminf(a[d], __shfl_down_sync(0xffffffffu, a[d], o));
                z[d] = fmaxf(z[d], __shfl_down_sync(0xffffffffu, z[d], o));
            }
            if (lane == 0) { s_lo[d] = a[d]; s_hi[d] = z[d]; }
        }
    }
    __syncthreads();

    // grid info (redundant per-thread; deterministic)
    int g[3];
    #pragma unroll
    for (int d = 0; d < 3; d++) {
        int gg = (int)floorf(__fdiv_rn(__fsub_rn(s_hi[d], s_lo[d]), RAD)) + 1;
        g[d] = max(1, min(GMAX, gg));
    }
    const int st1 = g[2];
    const int st0 = g[1] * g[2];
    int gdp = g[0] * g[1] * g[2];
    if (gdp > CMAXF) gdp = CMAXF;       // never hit for [0,1)^3 data
    if (t == 0) {
        GridInfo gi;
        gi.lx = s_lo[0]; gi.ly = s_lo[1]; gi.lz = s_lo[2];
        gi.g0 = g[0]; gi.g1 = g[1]; gi.g2 = g[2];
        gi.s0 = st0; gi.s1 = st1; gi.gdprod = gdp;
        g_grid[b] = gi;
    }

    // ---- 2) zero bins, cell ids, histogram ----
    for (int c = t; c < gdp; c += TPB) s_start[c] = 0;
    __syncthreads();
    for (int i = t; i < N; i += TPB) {
        int c[3];
        #pragma unroll
        for (int d = 0; d < 3; d++) {
            float v = s_loc[i * 3 + d];
            int cc = (int)floorf(__fdiv_rn(__fsub_rn(v, s_lo[d]), RAD));
            cc = max(0, min(g[d] - 1, cc));
            c[d] = cc;
        }
        int cid = c[0] * st0 + c[1] * st1 + c[2];
        if (cid >= gdp) cid = gdp - 1;
        s_cid[i] = cid;
        atomicAdd(&s_start[cid], 1);
    }
    __syncthreads();

    // ---- 3) exclusive scan ----
    if (gdp <= 1024) {
        int v = (t < gdp) ? s_start[t] : 0;
        int x = v;
        #pragma unroll
        for (int o = 1; o < 32; o <<= 1) {
            int y = __shfl_up_sync(0xffffffffu, x, o);
            if (lane >= o) x += y;
        }
        if (lane == 31) s_part[wid] = x;
        __syncthreads();
        if (wid == 0) {
            int w = s_part[lane];
            int xw = w;
            #pragma unroll
            for (int o = 1; o < 32; o <<= 1) {
                int y = __shfl_up_sync(0xffffffffu, xw, o);
                if (lane >= o) xw += y;
            }
            s_part[lane] = xw - w;
        }
        __syncthreads();
        int excl = x - v + s_part[wid];
        __syncthreads();
        if (t < gdp) s_start[t] = excl;
        if (t == 0) s_start[gdp] = N;
        __syncthreads();
    } else {
        const int E = (gdp + 1023) >> 10;
        int vals[8];
        int base = t * E;
        int sum = 0;
        #pragma unroll 8
        for (int e = 0; e < 8; e++) {
            int c = base + e;
            int v = (e < E && c < gdp) ? s_start[c] : 0;
            vals[e] = v; sum += v;
        }
        s_part[t] = sum;
        __syncthreads();
        for (int off = 1; off < 1024; off <<= 1) {
            int v = (t >= off) ? s_part[t - off] : 0;
            __syncthreads();
            s_part[t] += v;
            __syncthreads();
        }
        int run = s_part[t] - sum;
        #pragma unroll 8
        for (int e = 0; e < 8; e++) {
            int c = base + e;
            if (e < E && c < gdp) { s_start[c] = run; run += vals[e]; }
        }
        if (t == 0) s_start[gdp] = N;
        __syncthreads();
    }

    // emit g_start (+tail = N so collide lookups are always safe)
    for (int c = t; c <= CMAXF; c += TPB)
        g_start[b][c] = (c <= gdp) ? s_start[c] : N;
    __syncthreads();

    // ---- 4) scatter on s_start: afterwards s_start[c] = start[c+1] ----
    for (int i = t; i < N; i += TPB) {
        int pos = atomicAdd(&s_start[s_cid[i]], 1);
        s_idx[pos] = i;
    }
    __syncthreads();

    // ---- 5) per-cell insertion sort by original index => exact STABLE ----
    for (int c = t; c < gdp; c += TPB) {
        int lo = (c == 0) ? 0 : s_start[c - 1];
        int hi = s_start[c];
        for (int i = lo + 1; i < hi; i++) {
            int v = s_idx[i];
            int j = i - 1;
            while (j >= lo && s_idx[j] > v) { s_idx[j + 1] = s_idx[j]; j--; }
            s_idx[j + 1] = v;
        }
    }
    __syncthreads();

    // ---- 6) emit idxs + gathered locs ----
    for (int pos = t; pos < N; pos += TPB) {
        int i = s_idx[pos];
        g_idx[b][pos] = i;
        out_idxs[(size_t)b * N + pos] = (float)i;
        float x = s_loc[i * 3 + 0];
        float y = s_loc[i * 3 + 1];
        float z = s_loc[i * 3 + 2];
        float* o = out_nlocs + ((size_t)b * N + pos) * 3;
        o[0] = x; o[1] = y; o[2] = z;
        g_nlocs[b][pos] = make_float4(x, y, z, 0.f);
    }
}

// ---------------------------------------------------------------------------
// One query's collision list: flat-candidate, software-pipelined.
// The 9 (cx,cy) segments are disjoint and ascending in sorted index, so flat
// order == ascending j == exact reference order.
// ---------------------------------------------------------------------------
__device__ void collide_one(int w, int lane,
                            const float* __restrict__ qlocs,
                            float* __restrict__ out_nb, int B, int M)
{
    int b = w / M, m = w - b * M;
    const float* q = qlocs + ((size_t)b * M + m) * 3;
    float qx = q[0], qy = q[1], qz = q[2];

    GridInfo gi = g_grid[b];
    int cqx = (int)floorf(__fdiv_rn(__fsub_rn(qx, gi.lx), RAD));
    int cqy = (int)floorf(__fdiv_rn(__fsub_rn(qy, gi.ly), RAD));
    int cqz = (int)floorf(__fdiv_rn(__fsub_rn(qz, gi.lz), RAD));
    int z0 = max(0, cqz - 1), z1 = min(gi.g2 - 1, cqz + 1);

    const int* __restrict__ S = g_start[b];
    const float4* __restrict__ P = g_nlocs[b];
    float* outp = out_nb + (size_t)w * KMAX;

    // prefill whole row with -1, hits overwrite below
    ((float4*)outp)[lane] = make_float4(-1.f, -1.f, -1.f, -1.f);
    __syncwarp();

    // segment bounds + flat prefix offsets (all unrolled -> registers)
    int jlo[9], off[10];
    off[0] = 0;
    bool zok = (z0 <= z1);
    #pragma unroll
    for (int r = 0; r < 9; r++) {
        int cx = cqx + (r / 3) - 1;
        int cy = cqy + (r % 3) - 1;
        bool ok = zok && cx >= 0 && cx < gi.g0 && cy >= 0 && cy < gi.g1;
        int base = cx * gi.s0 + cy * gi.s1;
        int lo = ok ? S[base + z0] : 0;
        int hi = ok ? S[base + z1 + 1] : 0;
        jlo[r] = lo;
        off[r + 1] = off[r] + max(0, hi - lo);
    }
    int T = off[9];
    if (T == 0) return;

    // flat f -> sorted index j (fully unrolled compare/select chain)
    auto flat2j = [&](int f) -> int {
        int j = 0;
        #pragma unroll
        for (int r = 0; r < 9; r++)
            if (f >= off[r] && f < off[r + 1]) j = jlo[r] + (f - off[r]);
        return j;
    };

    int cnt = 0;
    int f0 = lane;
    int jcur = 0;
    float4 pcur = make_float4(0.f, 0.f, 0.f, 0.f);
    if (f0 < T) { jcur = flat2j(f0); pcur = P[jcur]; }

    for (int base = 0; base < T; base += 32) {
        // prefetch next round (address independent of this round's ballot)
        int fn = base + 32 + lane;
        int jnext = 0;
        float4 pnext = make_float4(0.f, 0.f, 0.f, 0.f);
        if (fn < T) { jnext = flat2j(fn); pnext = P[jnext]; }

        bool hit = false;
        if (base + lane < T) {
            float dx = __fsub_rn(qx, pcur.x);
            float dy = __fsub_rn(qy, pcur.y);
            float dz = __fsub_rn(qz, pcur.z);
            float d2 = __fadd_rn(__fadd_rn(__fmul_rn(dx, dx),
                                           __fmul_rn(dy, dy)),
                                 __fmul_rn(dz, dz));
            hit = (d2 <= RAD2);
        }
        unsigned msk = __ballot_sync(0xffffffffu, hit);
        if (hit) {
            int pos = cnt + __popc(msk & ((1u << lane) - 1u));
            if (pos < KMAX) outp[pos] = (float)jcur;
        }
        cnt += __popc(msk);
        if (cnt >= KMAX) break;
        pcur = pnext; jcur = jnext;
    }
}

// ---------------------------------------------------------------------------
// Persistent fused kernel: blocks 0..B-1 sort, everyone waits on flags, then
// all blocks grid-stride gather + collide. Flags reset by the last block.
// ---------------------------------------------------------------------------
__global__ __launch_bounds__(TPB, 1)
void fused_kernel(const float* __restrict__ locs,
                  const float4* __restrict__ data,
                  const float* __restrict__ qlocs,
                  float* __restrict__ out_idxs,
                  float* __restrict__ out_nlocs,
                  float4* __restrict__ out_ndata,
                  float* __restrict__ out_nb,
                  int B, int N, int C4, int M)
{
    extern __shared__ float shf[];
    const int t   = threadIdx.x;
    const int bId = blockIdx.x;

    // ---- phase 1: sort (blocks 0..B-1 only) ----
    if (bId < B) {
        sort_body(bId, locs, out_idxs, out_nlocs, N, shf);
        __syncthreads();
        if (t == 0) { __threadfence(); g_done[bId] = 1; }
    }

    // ---- wait for all batches' sorts ----
    if (t == 0) {
        for (int b2 = 0; b2 < B; b2++)
            while (g_done[b2] == 0) { __nanosleep(32); }
        __threadfence();
    }
    __syncthreads();

    const int totalThreads = gridDim.x * blockDim.x;
    const int gtid = bId * blockDim.x + t;

    // ---- phase 2a: gather reordered data (4 float4s per element) ----
    {
        int Q = C4 >> 2;
        int tot = B * N * Q;
        for (int e = gtid; e < tot; e += totalThreads) {
            int sub = e % Q;
            int bi  = e / Q;
            int b = bi / N, i = bi - b * N;
            int idx = __ldg(&g_idx[b][i]);
            const float4* src = data + (((size_t)b * N + idx) * C4) + sub * 4;
            float4* dst = out_ndata + ((size_t)bi * C4) + sub * 4;
            float4 v0 = src[0], v1 = src[1], v2 = src[2], v3 = src[3];
            dst[0] = v0; dst[1] = v1; dst[2] = v2; dst[3] = v3;
        }
    }

    // ---- phase 2b: collisions, one warp per query, grid-strided ----
    {
        int lane = t & 31;
        int gwarp = gtid >> 5;
        int totalWarps = totalThreads >> 5;
        for (int w = gwarp; w < B * M; w += totalWarps)
            collide_one(w, lane, qlocs, out_nb, B, M);
    }

    // ---- epilogue: last finishing block resets flags for next replay ----
    __syncthreads();
    if (t == 0) {
        __threadfence();
        int r = atomicAdd(&g_fin, 1);
        if (r == (int)gridDim.x - 1) {
            for (int b2 = 0; b2 < BMAX; b2++) g_done[b2] = 0;
            g_fin = 0;
            __threadfence();
        }
    }
}

// ---------------------------------------------------------------------------
extern "C" void kernel_launch(void* const* d_in, const int* in_sizes, int n_in,
                              void* d_out, int out_size)
{
    const float* locs  = (const float*)d_in[0];
    const float* data  = (const float*)d_in[1];
    const float* qlocs = (const float*)d_in[2];

    const int B = 2;                       // fixed by setup_inputs
    const int N = in_sizes[0] / (B * 3);
    const int C = in_sizes[1] / (B * N);
    const int M = in_sizes[2] / (B * 3);
    if (N > NMAX || B > BMAX) return;      // scratch bound guard (never hit)

    float* out       = (float*)d_out;
    float* out_nlocs = out;
    float* out_ndata = out_nlocs + (size_t)B * N * 3;
    float* out_idxs  = out_ndata + (size_t)B * N * C;
    float* out_nb    = out_idxs  + (size_t)B * N;

    size_t smem = (size_t)(NMAX * 3 + NMAX * 2 + (CMAXF + 1)) * sizeof(float);
    cudaFuncSetAttribute(fused_kernel,
                         cudaFuncAttributeMaxDynamicSharedMemorySize, (int)smem);

    fused_kernel<<<NBLK, TPB, smem>>>(locs, (const float4*)data, qlocs,
                                      out_idxs, out_nlocs,
                                      (float4*)out_ndata, out_nb,
                                      B, N, C / 4, M);
}

// round 8
// speedup vs baseline: 1.1819x; 1.1819x over previous
#include <cuda_runtime.h>
#include <math.h>
#include <float.h>

// Problem constants (fixed by setup_inputs)
#define BMAX 2
#define NMAX 8192
#define GMAX 96
#define KMAX 128
#define RAD  0.1f
#define RAD2 0.01f      // float32 nearest to python 0.1*0.1 (matches JAX)
#define CMAXF 8192      // max flattened cells supported (data -> gdprod = 1000)

struct GridInfo {
    float lx, ly, lz;
    int g0, g1, g2;
    int s0, s1;
    int gdprod;
};

__device__ GridInfo g_grid[BMAX];
__device__ int      g_idx[BMAX][NMAX];
__device__ float4   g_nlocs[BMAX][NMAX];
__device__ int      g_start[BMAX][CMAXF + 1];

// ---------------------------------------------------------------------------
// Fused sort kernel: one block per batch, 1024 threads, all phases in smem.
// smem: loc[3N] | cid[N] | idx[N] | start[CMAXF+1]  (~192KB dynamic)
// ---------------------------------------------------------------------------
__global__ __launch_bounds__(1024)
void sort_kernel(const float* __restrict__ locs,
                 float* __restrict__ out_idxs,
                 float* __restrict__ out_nlocs,
                 int N)
{
    extern __shared__ float shf[];
    float* s_loc  = shf;                          // [NMAX*3]
    int*  s_cid   = (int*)(s_loc + NMAX * 3);     // [NMAX]
    int*  s_idx   = s_cid + NMAX;                 // [NMAX]
    int*  s_start = s_idx + NMAX;                 // [CMAXF+1]
    int*  s_part  = s_idx;                        // alias: scan partials

    __shared__ float s_wmn[32][3], s_wmx[32][3];
    __shared__ float s_lo[3], s_hi[3];

    const int b = blockIdx.x;
    const int t = threadIdx.x;
    const int lane = t & 31;
    const int wid  = t >> 5;

    // ---- 0) stage locs into smem, coalesced float4 ----
    {
        const float* Lg = locs + (size_t)b * N * 3;
        int n4 = (N * 3) >> 2;
        const float4* L4 = (const float4*)Lg;
        float4* S4 = (float4*)s_loc;
        for (int k = t; k < n4; k += 1024) S4[k] = L4[k];
        for (int k = (n4 << 2) + t; k < N * 3; k += 1024) s_loc[k] = Lg[k];
    }
    __syncthreads();

    // ---- 1) min/max, warp shuffles ----
    float mn[3] = { FLT_MAX, FLT_MAX, FLT_MAX };
    float mx[3] = { -FLT_MAX, -FLT_MAX, -FLT_MAX };
    for (int i = t; i < N; i += 1024) {
        #pragma unroll
        for (int d = 0; d < 3; d++) {
            float v = s_loc[i * 3 + d];
            mn[d] = fminf(mn[d], v);
            mx[d] = fmaxf(mx[d], v);
        }
    }
    #pragma unroll
    for (int d = 0; d < 3; d++) {
        #pragma unroll
        for (int o = 16; o > 0; o >>= 1) {
            mn[d] = fminf(mn[d], __shfl_down_sync(0xffffffffu, mn[d], o));
            mx[d] = fmaxf(mx[d], __shfl_down_sync(0xffffffffu, mx[d], o));
        }
        if (lane == 0) { s_wmn[wid][d] = mn[d]; s_wmx[wid][d] = mx[d]; }
    }
    __syncthreads();
    if (wid == 0) {
        float a[3], z[3];
        #pragma unroll
        for (int d = 0; d < 3; d++) { a[d] = s_wmn[lane][d]; z[d] = s_wmx[lane][d]; }
        #pragma unroll
        for (int d = 0; d < 3; d++) {
            #pragma unroll
            for (int o = 16; o > 0; o >>= 1) {
                a[d] = fminf(a[d], __shfl_down_sync(0xffffffffu, a[d], o));
                z[d] = fmaxf(z[d], __shfl_down_sync(0xffffffffu, z[d], o));
            }
            if (lane == 0) { s_lo[d] = a[d]; s_hi[d] = z[d]; }
        }
    }
    __syncthreads();

    // grid info (redundant per-thread; deterministic)
    int g[3];
    #pragma unroll
    for (int d = 0; d < 3; d++) {
        int gg = (int)floorf(__fdiv_rn(__fsub_rn(s_hi[d], s_lo[d]), RAD)) + 1;
        g[d] = max(1, min(GMAX, gg));
    }
    const int st1 = g[2];
    const int st0 = g[1] * g[2];
    int gdp = g[0] * g[1] * g[2];
    if (gdp > CMAXF) gdp = CMAXF;       // never hit for [0,1)^3 data
    if (t == 0) {
        GridInfo gi;
        gi.lx = s_lo[0]; gi.ly = s_lo[1]; gi.lz = s_lo[2];
        gi.g0 = g[0]; gi.g1 = g[1]; gi.g2 = g[2];
        gi.s0 = st0; gi.s1 = st1; gi.gdprod = gdp;
        g_grid[b] = gi;
    }

    // ---- 2) zero bins, cell ids, histogram ----
    for (int c = t; c < gdp; c += 1024) s_start[c] = 0;
    __syncthreads();
    for (int i = t; i < N; i += 1024) {
        int c[3];
        #pragma unroll
        for (int d = 0; d < 3; d++) {
            float v = s_loc[i * 3 + d];
            int cc = (int)floorf(__fdiv_rn(__fsub_rn(v, s_lo[d]), RAD));
            cc = max(0, min(g[d] - 1, cc));
            c[d] = cc;
        }
        int cid = c[0] * st0 + c[1] * st1 + c[2];
        if (cid >= gdp) cid = gdp - 1;
        s_cid[i] = cid;
        atomicAdd(&s_start[cid], 1);
    }
    __syncthreads();

    // ---- 3) exclusive scan ----
    if (gdp <= 1024) {
        int v = (t < gdp) ? s_start[t] : 0;
        int x = v;
        #pragma unroll
        for (int o = 1; o < 32; o <<= 1) {
            int y = __shfl_up_sync(0xffffffffu, x, o);
            if (lane >= o) x += y;
        }
        if (lane == 31) s_part[wid] = x;
        __syncthreads();
        if (wid == 0) {
            int w = s_part[lane];
            int xw = w;
            #pragma unroll
            for (int o = 1; o < 32; o <<= 1) {
                int y = __shfl_up_sync(0xffffffffu, xw, o);
                if (lane >= o) xw += y;
            }
            s_part[lane] = xw - w;
        }
        __syncthreads();
        int excl = x - v + s_part[wid];
        __syncthreads();
        if (t < gdp) s_start[t] = excl;
        if (t == 0) s_start[gdp] = N;
        __syncthreads();
    } else {
        const int E = (gdp + 1023) >> 10;
        int vals[8];
        int base = t * E;
        int sum = 0;
        #pragma unroll 8
        for (int e = 0; e < 8; e++) {
            int c = base + e;
            int v = (e < E && c < gdp) ? s_start[c] : 0;
            vals[e] = v; sum += v;
        }
        s_part[t] = sum;
        __syncthreads();
        for (int off = 1; off < 1024; off <<= 1) {
            int v = (t >= off) ? s_part[t - off] : 0;
            __syncthreads();
            s_part[t] += v;
            __syncthreads();
        }
        int run = s_part[t] - sum;
        #pragma unroll 8
        for (int e = 0; e < 8; e++) {
            int c = base + e;
            if (e < E && c < gdp) { s_start[c] = run; run += vals[e]; }
        }
        if (t == 0) s_start[gdp] = N;
        __syncthreads();
    }

    // emit g_start[0..gdp] (collide only indexes within bounds-guarded cells)
    for (int c = t; c <= gdp; c += 1024)
        g_start[b][c] = s_start[c];
    __syncthreads();

    // ---- 4) scatter on s_start: afterwards s_start[c] = start[c+1] ----
    for (int i = t; i < N; i += 1024) {
        int pos = atomicAdd(&s_start[s_cid[i]], 1);
        s_idx[pos] = i;
    }
    __syncthreads();

    // ---- 5) per-cell insertion sort by original index => exact STABLE ----
    for (int c = t; c < gdp; c += 1024) {
        int lo = (c == 0) ? 0 : s_start[c - 1];
        int hi = s_start[c];
        for (int i = lo + 1; i < hi; i++) {
            int v = s_idx[i];
            int j = i - 1;
            while (j >= lo && s_idx[j] > v) { s_idx[j + 1] = s_idx[j]; j--; }
            s_idx[j + 1] = v;
        }
    }
    __syncthreads();

    // ---- 6) emit idxs + gathered locs ----
    for (int pos = t; pos < N; pos += 1024) {
        int i = s_idx[pos];
        g_idx[b][pos] = i;
        out_idxs[(size_t)b * N + pos] = (float)i;
        float x = s_loc[i * 3 + 0];
        float y = s_loc[i * 3 + 1];
        float z = s_loc[i * 3 + 2];
        float* o = out_nlocs + ((size_t)b * N + pos) * 3;
        o[0] = x; o[1] = y; o[2] = z;
        g_nlocs[b][pos] = make_float4(x, y, z, 0.f);
    }
}

// ---------------------------------------------------------------------------
// Fused tail: collide blocks first (longer-running), then gather blocks.
// Collide: flat-candidate, software-pipelined (proven exact in R6).
// ---------------------------------------------------------------------------
__global__ void tail_kernel(const float4* __restrict__ data,
                            const float* __restrict__ qlocs,
                            float4* __restrict__ out_ndata,
                            float* __restrict__ out_nb,
                            int B, int N, int C4, int M, int collideBlocks)
{
    if ((int)blockIdx.x >= collideBlocks) {
        // ---------------- gather: 4 float4s per thread ----------------
        int Q = C4 >> 2;
        int t = (blockIdx.x - collideBlocks) * blockDim.x + threadIdx.x;
        if (t >= B * N * Q) return;
        int sub = t % Q;
        int bi  = t / Q;
        int b = bi / N, i = bi - b * N;
        int idx = __ldg(&g_idx[b][i]);
        const float4* src = data + (((size_t)b * N + idx) * C4) + sub * 4;
        float4* dst = out_ndata + ((size_t)bi * C4) + sub * 4;
        float4 v0 = src[0], v1 = src[1], v2 = src[2], v3 = src[3];
        dst[0] = v0; dst[1] = v1; dst[2] = v2; dst[3] = v3;
        return;
    }

    // ---------------- collide: one warp per query ----------------
    int gt   = blockIdx.x * blockDim.x + threadIdx.x;
    int w    = gt >> 5;
    int lane = gt & 31;
    if (w >= B * M) return;
    int b = w / M, m = w - b * M;

    const float* q = qlocs + ((size_t)b * M + m) * 3;
    float qx = q[0], qy = q[1], qz = q[2];

    GridInfo gi = g_grid[b];
    int cqx = (int)floorf(__fdiv_rn(__fsub_rn(qx, gi.lx), RAD));
    int cqy = (int)floorf(__fdiv_rn(__fsub_rn(qy, gi.ly), RAD));
    int cqz = (int)floorf(__fdiv_rn(__fsub_rn(qz, gi.lz), RAD));
    int z0 = max(0, cqz - 1), z1 = min(gi.g2 - 1, cqz + 1);

    const int* __restrict__ S = g_start[b];
    const float4* __restrict__ P = g_nlocs[b];
    float* outp = out_nb + (size_t)w * KMAX;

    // prefill whole row with -1 (one float4 per lane), hits overwrite below
    ((float4*)outp)[lane] = make_float4(-1.f, -1.f, -1.f, -1.f);
    __syncwarp();

    // segment bounds + flat prefix offsets (fully unrolled -> registers)
    int jlo[9], off[10];
    off[0] = 0;
    bool zok = (z0 <= z1);
    #pragma unroll
    for (int r = 0; r < 9; r++) {
        int cx = cqx + (r / 3) - 1;
        int cy = cqy + (r % 3) - 1;
        bool ok = zok && cx >= 0 && cx < gi.g0 && cy >= 0 && cy < gi.g1;
        int base = cx * gi.s0 + cy * gi.s1;
        int lo = ok ? S[base + z0] : 0;
        int hi = ok ? S[base + z1 + 1] : 0;
        jlo[r] = lo;
        off[r + 1] = off[r] + max(0, hi - lo);
    }
    int T = off[9];
    if (T == 0) return;

    // flat f -> sorted index j (unrolled compare/select chain)
    auto flat2j = [&](int f) -> int {
        int j = 0;
        #pragma unroll
        for (int r = 0; r < 9; r++)
            if (f >= off[r] && f < off[r + 1]) j = jlo[r] + (f - off[r]);
        return j;
    };

    int cnt = 0;
    int jcur = 0;
    float4 pcur = make_float4(0.f, 0.f, 0.f, 0.f);
    if (lane < T) { jcur = flat2j(lane); pcur = P[jcur]; }

    for (int base = 0; base < T; base += 32) {
        // prefetch next round (address independent of this round's ballot)
        int fn = base + 32 + lane;
        int jnext = 0;
        float4 pnext = make_float4(0.f, 0.f, 0.f, 0.f);
        if (fn < T) { jnext = flat2j(fn); pnext = P[jnext]; }

        bool hit = false;
        if (base + lane < T) {
            float dx = __fsub_rn(qx, pcur.x);
            float dy = __fsub_rn(qy, pcur.y);
            float dz = __fsub_rn(qz, pcur.z);
            float d2 = __fadd_rn(__fadd_rn(__fmul_rn(dx, dx),
                                           __fmul_rn(dy, dy)),
                                 __fmul_rn(dz, dz));
            hit = (d2 <= RAD2);
        }
        unsigned msk = __ballot_sync(0xffffffffu, hit);
        if (hit) {
            int pos = cnt + __popc(msk & ((1u << lane) - 1u));
            if (pos < KMAX) outp[pos] = (float)jcur;
        }
        cnt += __popc(msk);
        if (cnt >= KMAX) break;
        pcur = pnext; jcur = jnext;
    }
}

// ---------------------------------------------------------------------------
extern "C" void kernel_launch(void* const* d_in, const int* in_sizes, int n_in,
                              void* d_out, int out_size)
{
    const float* locs  = (const float*)d_in[0];
    const float* data  = (const float*)d_in[1];
    const float* qlocs = (const float*)d_in[2];

    const int B = 2;                       // fixed by setup_inputs
    const int N = in_sizes[0] / (B * 3);
    const int C = in_sizes[1] / (B * N);
    const int M = in_sizes[2] / (B * 3);
    if (N > NMAX || B > BMAX) return;      // scratch bound guard (never hit)

    float* out       = (float*)d_out;
    float* out_nlocs = out;
    float* out_ndata = out_nlocs + (size_t)B * N * 3;
    float* out_idxs  = out_ndata + (size_t)B * N * C;
    float* out_nb    = out_idxs  + (size_t)B * N;

    size_t smem = (size_t)(NMAX * 3 + NMAX * 2 + (CMAXF + 1)) * sizeof(float);
    cudaFuncSetAttribute(sort_kernel,
                         cudaFuncAttributeMaxDynamicSharedMemorySize, (int)smem);
    sort_kernel<<<B, 1024, smem>>>(locs, out_idxs, out_nlocs, N);

    const int TPB = 256;
    int C4 = C / 4;
    int Q  = C4 / 4;
    int collideBlocks = (B * M * 32 + TPB - 1) / TPB;
    int gatherBlocks  = (B * N * Q + TPB - 1) / TPB;
    tail_kernel<<<collideBlocks + gatherBlocks, TPB>>>(
        (const float4*)data, qlocs, (float4*)out_ndata, out_nb,
        B, N, C4, M, collideBlocks);
}

// round 9
// speedup vs baseline: 1.3861x; 1.1728x over previous
#include <cuda_runtime.h>
#include <math.h>
#include <float.h>

// Problem constants (fixed by setup_inputs)
#define BMAX 2
#define NMAX 8192
#define GMAX 96
#define KMAX 128
#define RAD  0.1f
#define RAD2 0.01f      // float32 nearest to python 0.1*0.1 (matches JAX)
#define CMAXF 8192      // max flattened cells supported (data -> gdprod = 1000)

struct GridInfo {
    float lx, ly, lz;
    int g0, g1, g2;
    int s0, s1;
    int gdprod;
};

__device__ GridInfo g_grid[BMAX];
__device__ int      g_idx[BMAX][NMAX];
__device__ float4   g_nlocs[BMAX][NMAX];
__device__ int      g_start[BMAX][CMAXF + 1];

// ---------------------------------------------------------------------------
// Fused sort kernel: one block per batch, 1024 threads, all phases in smem.
// Emits only g_idx / g_nlocs / g_start; out_* emission moved to tail.
// smem: loc[3N] | cid[N] | idx[N] | start[CMAXF+1]  (~192KB dynamic)
// ---------------------------------------------------------------------------
__global__ __launch_bounds__(1024)
void sort_kernel(const float* __restrict__ locs, int N)
{
    extern __shared__ float shf[];
    float* s_loc  = shf;                          // [NMAX*3]
    int*  s_cid   = (int*)(s_loc + NMAX * 3);     // [NMAX]
    int*  s_idx   = s_cid + NMAX;                 // [NMAX]
    int*  s_start = s_idx + NMAX;                 // [CMAXF+1]
    int*  s_part  = s_idx;                        // alias: scan partials

    __shared__ float s_wmn[32][3], s_wmx[32][3];
    __shared__ float s_lo[3], s_hi[3];

    const int b = blockIdx.x;
    const int t = threadIdx.x;
    const int lane = t & 31;
    const int wid  = t >> 5;

    // ---- 0) stage locs into smem, coalesced float4 ----
    {
        const float* Lg = locs + (size_t)b * N * 3;
        int n4 = (N * 3) >> 2;
        const float4* L4 = (const float4*)Lg;
        float4* S4 = (float4*)s_loc;
        for (int k = t; k < n4; k += 1024) S4[k] = L4[k];
        for (int k = (n4 << 2) + t; k < N * 3; k += 1024) s_loc[k] = Lg[k];
    }
    __syncthreads();

    // ---- 1) min/max, warp shuffles ----
    float mn[3] = { FLT_MAX, FLT_MAX, FLT_MAX };
    float mx[3] = { -FLT_MAX, -FLT_MAX, -FLT_MAX };
    for (int i = t; i < N; i += 1024) {
        #pragma unroll
        for (int d = 0; d < 3; d++) {
            float v = s_loc[i * 3 + d];
            mn[d] = fminf(mn[d], v);
            mx[d] = fmaxf(mx[d], v);
        }
    }
    #pragma unroll
    for (int d = 0; d < 3; d++) {
        #pragma unroll
        for (int o = 16; o > 0; o >>= 1) {
            mn[d] = fminf(mn[d], __shfl_down_sync(0xffffffffu, mn[d], o));
            mx[d] = fmaxf(mx[d], __shfl_down_sync(0xffffffffu, mx[d], o));
        }
        if (lane == 0) { s_wmn[wid][d] = mn[d]; s_wmx[wid][d] = mx[d]; }
    }
    __syncthreads();
    if (wid == 0) {
        float a[3], z[3];
        #pragma unroll
        for (int d = 0; d < 3; d++) { a[d] = s_wmn[lane][d]; z[d] = s_wmx[lane][d]; }
        #pragma unroll
        for (int d = 0; d < 3; d++) {
            #pragma unroll
            for (int o = 16; o > 0; o >>= 1) {
                a[d] = fminf(a[d], __shfl_down_sync(0xffffffffu, a[d], o));
                z[d] = fmaxf(z[d], __shfl_down_sync(0xffffffffu, z[d], o));
            }
            if (lane == 0) { s_lo[d] = a[d]; s_hi[d] = z[d]; }
        }
    }
    __syncthreads();

    // grid info (redundant per-thread; deterministic)
    int g[3];
    #pragma unroll
    for (int d = 0; d < 3; d++) {
        int gg = (int)floorf(__fdiv_rn(__fsub_rn(s_hi[d], s_lo[d]), RAD)) + 1;
        g[d] = max(1, min(GMAX, gg));
    }
    const int st1 = g[2];
    const int st0 = g[1] * g[2];
    int gdp = g[0] * g[1] * g[2];
    if (gdp > CMAXF) gdp = CMAXF;       // never hit for [0,1)^3 data
    if (t == 0) {
        GridInfo gi;
        gi.lx = s_lo[0]; gi.ly = s_lo[1]; gi.lz = s_lo[2];
        gi.g0 = g[0]; gi.g1 = g[1]; gi.g2 = g[2];
        gi.s0 = st0; gi.s1 = st1; gi.gdprod = gdp;
        g_grid[b] = gi;
    }

    // ---- 2) zero bins, cell ids, histogram ----
    for (int c = t; c < gdp; c += 1024) s_start[c] = 0;
    __syncthreads();
    for (int i = t; i < N; i += 1024) {
        int c[3];
        #pragma unroll
        for (int d = 0; d < 3; d++) {
            float v = s_loc[i * 3 + d];
            int cc = (int)floorf(__fdiv_rn(__fsub_rn(v, s_lo[d]), RAD));
            cc = max(0, min(g[d] - 1, cc));
            c[d] = cc;
        }
        int cid = c[0] * st0 + c[1] * st1 + c[2];
        if (cid >= gdp) cid = gdp - 1;
        s_cid[i] = cid;
        atomicAdd(&s_start[cid], 1);
    }
    __syncthreads();

    // ---- 3) exclusive scan ----
    if (gdp <= 1024) {
        int v = (t < gdp) ? s_start[t] : 0;
        int x = v;
        #pragma unroll
        for (int o = 1; o < 32; o <<= 1) {
            int y = __shfl_up_sync(0xffffffffu, x, o);
            if (lane >= o) x += y;
        }
        if (lane == 31) s_part[wid] = x;
        __syncthreads();
        if (wid == 0) {
            int w = s_part[lane];
            int xw = w;
            #pragma unroll
            for (int o = 1; o < 32; o <<= 1) {
                int y = __shfl_up_sync(0xffffffffu, xw, o);
                if (lane >= o) xw += y;
            }
            s_part[lane] = xw - w;
        }
        __syncthreads();
        int excl = x - v + s_part[wid];
        __syncthreads();
        if (t < gdp) s_start[t] = excl;
        if (t == 0) s_start[gdp] = N;
        __syncthreads();
    } else {
        const int E = (gdp + 1023) >> 10;
        int vals[8];
        int base = t * E;
        int sum = 0;
        #pragma unroll 8
        for (int e = 0; e < 8; e++) {
            int c = base + e;
            int v = (e < E && c < gdp) ? s_start[c] : 0;
            vals[e] = v; sum += v;
        }
        s_part[t] = sum;
        __syncthreads();
        for (int off = 1; off < 1024; off <<= 1) {
            int v = (t >= off) ? s_part[t - off] : 0;
            __syncthreads();
            s_part[t] += v;
            __syncthreads();
        }
        int run = s_part[t] - sum;
        #pragma unroll 8
        for (int e = 0; e < 8; e++) {
            int c = base + e;
            if (e < E && c < gdp) { s_start[c] = run; run += vals[e]; }
        }
        if (t == 0) s_start[gdp] = N;
        __syncthreads();
    }

    // emit g_start[0..gdp]
    for (int c = t; c <= gdp; c += 1024)
        g_start[b][c] = s_start[c];
    __syncthreads();

    // ---- 4) scatter on s_start: afterwards s_start[c] = start[c+1] ----
    for (int i = t; i < N; i += 1024) {
        int pos = atomicAdd(&s_start[s_cid[i]], 1);
        s_idx[pos] = i;
    }
    __syncthreads();

    // ---- 5) per-cell insertion sort by original index => exact STABLE ----
    for (int c = t; c < gdp; c += 1024) {
        int lo = (c == 0) ? 0 : s_start[c - 1];
        int hi = s_start[c];
        for (int i = lo + 1; i < hi; i++) {
            int v = s_idx[i];
            int j = i - 1;
            while (j >= lo && s_idx[j] > v) { s_idx[j + 1] = s_idx[j]; j--; }
            s_idx[j + 1] = v;
        }
    }
    __syncthreads();

    // ---- 6) emit g_idx + g_nlocs only (out_* moved to tail) ----
    for (int pos = t; pos < N; pos += 1024) {
        int i = s_idx[pos];
        g_idx[b][pos] = i;
        float x = s_loc[i * 3 + 0];
        float y = s_loc[i * 3 + 1];
        float z = s_loc[i * 3 + 2];
        g_nlocs[b][pos] = make_float4(x, y, z, 0.f);
    }
}

// ---------------------------------------------------------------------------
// Fused tail: [collide blocks | emit blocks | gather blocks]
// ---------------------------------------------------------------------------
__global__ void tail_kernel(const float4* __restrict__ data,
                            const float* __restrict__ qlocs,
                            float* __restrict__ out_nlocs,
                            float4* __restrict__ out_ndata,
                            float* __restrict__ out_idxs,
                            float* __restrict__ out_nb,
                            int B, int N, int C4, int M,
                            int collideBlocks, int emitBlocks)
{
    int bx = blockIdx.x;
    if (bx >= collideBlocks) {
        bx -= collideBlocks;
        if (bx < emitBlocks) {
            // -------- emit out_idxs + out_nlocs from g_idx/g_nlocs --------
            int t = bx * blockDim.x + threadIdx.x;
            if (t >= B * N) return;
            int b = t / N, pos = t - b * N;
            float4 p = g_nlocs[b][pos];
            float* o = out_nlocs + (size_t)t * 3;
            o[0] = p.x; o[1] = p.y; o[2] = p.z;
            out_idxs[t] = (float)__ldg(&g_idx[b][pos]);
            return;
        }
        // ---------------- gather: 4 float4s per thread ----------------
        int Q = C4 >> 2;
        int t = (bx - emitBlocks) * blockDim.x + threadIdx.x;
        if (t >= B * N * Q) return;
        int sub = t % Q;
        int bi  = t / Q;
        int b = bi / N, i = bi - b * N;
        int idx = __ldg(&g_idx[b][i]);
        const float4* src = data + (((size_t)b * N + idx) * C4) + sub * 4;
        float4* dst = out_ndata + ((size_t)bi * C4) + sub * 4;
        float4 v0 = src[0], v1 = src[1], v2 = src[2], v3 = src[3];
        dst[0] = v0; dst[1] = v1; dst[2] = v2; dst[3] = v3;
        return;
    }

    // ---------------- collide: one warp per query ----------------
    int gt   = blockIdx.x * blockDim.x + threadIdx.x;
    int w    = gt >> 5;
    int lane = gt & 31;
    if (w >= B * M) return;
    int b = w / M, m = w - b * M;

    const float* q = qlocs + ((size_t)b * M + m) * 3;
    float qx = q[0], qy = q[1], qz = q[2];

    GridInfo gi = g_grid[b];
    int cqx = (int)floorf(__fdiv_rn(__fsub_rn(qx, gi.lx), RAD));
    int cqy = (int)floorf(__fdiv_rn(__fsub_rn(qy, gi.ly), RAD));
    int cqz = (int)floorf(__fdiv_rn(__fsub_rn(qz, gi.lz), RAD));
    int z0 = max(0, cqz - 1), z1 = min(gi.g2 - 1, cqz + 1);

    const int* __restrict__ S = g_start[b];
    const float4* __restrict__ P = g_nlocs[b];
    float* outp = out_nb + (size_t)w * KMAX;

    // prefill whole row with -1 (one float4 per lane), hits overwrite below
    ((float4*)outp)[lane] = make_float4(-1.f, -1.f, -1.f, -1.f);
    __syncwarp();

    // segment bounds (18 concurrent LDGs)
    int jlo[9], jhi[9];
    bool zok = (z0 <= z1);
    #pragma unroll
    for (int r = 0; r < 9; r++) {
        int cx = cqx + (r / 3) - 1;
        int cy = cqy + (r % 3) - 1;
        bool ok = zok && cx >= 0 && cx < gi.g0 && cy >= 0 && cy < gi.g1;
        int base = cx * gi.s0 + cy * gi.s1;
        jlo[r] = ok ? S[base + z0] : 0;
        jhi[r] = ok ? S[base + z1 + 1] : 0;
    }

    // prefetch FIRST round of every segment upfront (9 concurrent LDGs;
    // addresses independent of any ballot result)
    float4 pre[9];
    #pragma unroll
    for (int r = 0; r < 9; r++) {
        int j = jlo[r] + lane;
        pre[r] = (j < jhi[r]) ? P[j]
                              : make_float4(1e30f, 1e30f, 1e30f, 0.f);
    }

    int cnt = 0;
    #pragma unroll
    for (int r = 0; r < 9; r++) {
        int lo = jlo[r], hi = jhi[r];
        if (lo >= hi) continue;
        // round 0: uses prefetched value
        {
            int j = lo + lane;
            bool hit = false;
            if (j < hi) {
                float dx = __fsub_rn(qx, pre[r].x);
                float dy = __fsub_rn(qy, pre[r].y);
                float dz = __fsub_rn(qz, pre[r].z);
                float d2 = __fadd_rn(__fadd_rn(__fmul_rn(dx, dx),
                                               __fmul_rn(dy, dy)),
                                     __fmul_rn(dz, dz));
                hit = (d2 <= RAD2);
            }
            unsigned msk = __ballot_sync(0xffffffffu, hit);
            if (hit) {
                int pos = cnt + __popc(msk & ((1u << lane) - 1u));
                if (pos < KMAX) outp[pos] = (float)j;
            }
            cnt += __popc(msk);
        }
        // rare overflow rounds (segment longer than 32)
        for (int j0 = lo + 32; j0 < hi; j0 += 32) {
            int j = j0 + lane;
            bool hit = false;
            if (j < hi) {
                float4 p = P[j];
                float dx = __fsub_rn(qx, p.x);
                float dy = __fsub_rn(qy, p.y);
                float dz = __fsub_rn(qz, p.z);
                float d2 = __fadd_rn(__fadd_rn(__fmul_rn(dx, dx),
                                               __fmul_rn(dy, dy)),
                                     __fmul_rn(dz, dz));
                hit = (d2 <= RAD2);
            }
            unsigned msk = __ballot_sync(0xffffffffu, hit);
            if (hit) {
                int pos = cnt + __popc(msk & ((1u << lane) - 1u));
                if (pos < KMAX) outp[pos] = (float)j;
            }
            cnt += __popc(msk);
        }
    }
}

// ---------------------------------------------------------------------------
extern "C" void kernel_launch(void* const* d_in, const int* in_sizes, int n_in,
                              void* d_out, int out_size)
{
    const float* locs  = (const float*)d_in[0];
    const float* data  = (const float*)d_in[1];
    const float* qlocs = (const float*)d_in[2];

    const int B = 2;                       // fixed by setup_inputs
    const int N = in_sizes[0] / (B * 3);
    const int C = in_sizes[1] / (B * N);
    const int M = in_sizes[2] / (B * 3);
    if (N > NMAX || B > BMAX) return;      // scratch bound guard (never hit)

    float* out       = (float*)d_out;
    float* out_nlocs = out;
    float* out_ndata = out_nlocs + (size_t)B * N * 3;
    float* out_idxs  = out_ndata + (size_t)B * N * C;
    float* out_nb    = out_idxs  + (size_t)B * N;

    size_t smem = (size_t)(NMAX * 3 + NMAX * 2 + (CMAXF + 1)) * sizeof(float);
    cudaFuncSetAttribute(sort_kernel,
                         cudaFuncAttributeMaxDynamicSharedMemorySize, (int)smem);
    sort_kernel<<<B, 1024, smem>>>(locs, N);

    const int TPB = 256;
    int C4 = C / 4;
    int Q  = C4 / 4;
    int collideBlocks = (B * M * 32 + TPB - 1) / TPB;
    int emitBlocks    = (B * N + TPB - 1) / TPB;
    int gatherBlocks  = (B * N * Q + TPB - 1) / TPB;
    tail_kernel<<<collideBlocks + emitBlocks + gatherBlocks, TPB>>>(
        (const float4*)data, qlocs, out_nlocs, (float4*)out_ndata,
        out_idxs, out_nb, B, N, C4, M, collideBlocks, emitBlocks);
}